// round 2
// baseline (speedup 1.0000x reference)
#include <cuda_runtime.h>
#include <cstddef>

#define FULLMASK 0xffffffffu

// Scratch for tok2 between the two kernels: 16384 * 49 * 16 floats = 51.4 MB
static __device__ float g_tok2[16384 * 49 * 16];

// ---------------------------------------------------------------------------
// Kernel A: grayscale -> patches -> QKV1 (pos-emb folded to bias) -> attn ->
// softmax -> tok2 (global scratch)
//
// SMEM layout (floats):
//   sW  [3][49][16][16]   : 37632   (layout [w][s][i][o], o = lane)
//   sB  [3][49][16]       : 2352    (pos-emb-folded biases)
//   sP  [8 warps][2][49][16] : 12544 (per-warp patch scratch)
// total = 52528 floats = 210112 B
// ---------------------------------------------------------------------------
__global__ void __launch_bounds__(256, 1) vitA(
    const float* __restrict__ x,
    const float* __restrict__ pe,
    const float* __restrict__ WQ1,
    const float* __restrict__ WK1,
    const float* __restrict__ WV1)
{
    extern __shared__ float sm[];
    float* sW = sm;                 // 3 * 12544
    float* sB = sm + 37632;         // 3 * 784
    float* sP = sm + 37632 + 2352;  // 8 * 1568

    const int tid = threadIdx.x;

    // ---- stage weights into SMEM, fold pos_emb into bias ----
    {
        const float* Wg[3] = {WQ1, WK1, WV1};
        for (int w = 0; w < 3; ++w) {
            const float* G = Wg[w];
            float* dst = sW + w * 12544;
            for (int idx = tid; idx < 12544; idx += 256) {
                int s = idx >> 8, r = idx & 255, i = r >> 4, o = r & 15;
                dst[s * 256 + i * 16 + o] = G[(s * 16 + o) * 32 + i];
            }
            float* db = sB + w * 784;
            for (int idx = tid; idx < 784; idx += 256) {
                int s = idx >> 4, o = idx & 15;
                const float* gw = G + (s * 16 + o) * 32 + 16;
                const float* pp = pe + s * 16;
                float acc = 0.f;
#pragma unroll
                for (int j = 0; j < 16; ++j) acc = fmaf(pp[j], gw[j], acc);
                db[idx] = acc;
            }
        }
    }
    __syncthreads();

    const int warpId = tid >> 5;
    const int lane = tid & 31;
    const int hh = lane >> 4;     // which element of the pair
    const int l16 = lane & 15;    // output dim d
    float* myP = sP + warpId * 1568 + hh * 784;
    const int totalW = gridDim.x * 8;

    for (int pair = blockIdx.x * 8 + warpId; pair < 8192; pair += totalW) {
        const int b = pair * 2 + hh;
        const float* xb = x + (size_t)b * 2352;

        // ---- grayscale + scatter to patch-major SMEM ----
#pragma unroll 1
        for (int it = 0; it < 49; ++it) {
            int p = it * 16 + l16;  // 0..783 linear pixel
            float g = 0.299f * xb[p] + 0.587f * xb[784 + p] + 0.114f * xb[1568 + p];
            int py = p / 28, px = p - py * 28;
            myP[((py >> 2) * 7 + (px >> 2)) * 16 + ((py & 3) << 2) + (px & 3)] = g;
        }
        __syncwarp();

        // ---- pass 1: q,k per patch; accumulate S[d][e] ----
        float S[16];
#pragma unroll
        for (int e = 0; e < 16; ++e) S[e] = 0.f;

#pragma unroll 1
        for (int s = 0; s < 49; ++s) {
            float pp[16];
            const float4* pv = (const float4*)(myP + s * 16);
#pragma unroll
            for (int t4 = 0; t4 < 4; ++t4) {
                float4 f = pv[t4];
                pp[t4 * 4 + 0] = f.x; pp[t4 * 4 + 1] = f.y;
                pp[t4 * 4 + 2] = f.z; pp[t4 * 4 + 3] = f.w;
            }
            const float* wq = sW + s * 256 + l16;
            const float* wk = wq + 12544;
            float q0 = sB[s * 16 + l16], q1 = 0.f;
            float k0 = sB[784 + s * 16 + l16], k1 = 0.f;
#pragma unroll
            for (int i = 0; i < 16; i += 2) {
                q0 = fmaf(pp[i], wq[i * 16], q0);
                q1 = fmaf(pp[i + 1], wq[(i + 1) * 16], q1);
                k0 = fmaf(pp[i], wk[i * 16], k0);
                k1 = fmaf(pp[i + 1], wk[(i + 1) * 16], k1);
            }
            float q = q0 + q1;
            float k = k0 + k1;
#pragma unroll
            for (int e = 0; e < 16; ++e) {
                float ke = __shfl_sync(FULLMASK, k, e, 16);
                S[e] = fmaf(q, ke, S[e]);
            }
        }
#pragma unroll
        for (int e = 0; e < 16; ++e) S[e] *= (1.f / 7.f);

        // ---- pass 2: recompute v, apply S, softmax over d, write tok2 ----
        float* ob = g_tok2 + (size_t)b * 784;
#pragma unroll 1
        for (int s = 0; s < 49; ++s) {
            float pp[16];
            const float4* pv = (const float4*)(myP + s * 16);
#pragma unroll
            for (int t4 = 0; t4 < 4; ++t4) {
                float4 f = pv[t4];
                pp[t4 * 4 + 0] = f.x; pp[t4 * 4 + 1] = f.y;
                pp[t4 * 4 + 2] = f.z; pp[t4 * 4 + 3] = f.w;
            }
            const float* wv = sW + 25088 + s * 256 + l16;
            float v0 = sB[1568 + s * 16 + l16], v1 = 0.f;
#pragma unroll
            for (int i = 0; i < 16; i += 2) {
                v0 = fmaf(pp[i], wv[i * 16], v0);
                v1 = fmaf(pp[i + 1], wv[(i + 1) * 16], v1);
            }
            float v = v0 + v1;
            float o = 0.f;
#pragma unroll
            for (int e = 0; e < 16; ++e) {
                float ve = __shfl_sync(FULLMASK, v, e, 16);
                o = fmaf(S[e], ve, o);
            }
            // softmax over the 16 lanes (dim d)
            float m = o;
#pragma unroll
            for (int dd = 8; dd; dd >>= 1)
                m = fmaxf(m, __shfl_xor_sync(FULLMASK, m, dd, 16));
            float ex = __expf(o - m);
            float sum = ex;
#pragma unroll
            for (int dd = 8; dd; dd >>= 1)
                sum += __shfl_xor_sync(FULLMASK, sum, dd, 16);
            ob[s * 16 + l16] = __fdividef(ex, sum);
        }
    }
}

// ---------------------------------------------------------------------------
// Kernel B: tok2 -> QKV2 -> attn(8) -> softmax -> tok3 -> fc1 -> relu -> fc2
// -> softmax -> out
//
// SMEM layout (floats):
//   sW2 [3][49][136]  : 19992  (pad stride 136 => sub-group banks disjoint)
//   sF1 [392][16]     : 6272
//   sF2 [16][10]      : 160
//   sB1 [16]          : 16
//   sB2 [16]          : 16 (10 used)
//   sT3 [8 warps][2][49][8] : 6272
// total = 32728 floats = 130912 B
// ---------------------------------------------------------------------------
__global__ void __launch_bounds__(256, 1) vitB(
    const float* __restrict__ WQ2,
    const float* __restrict__ WK2,
    const float* __restrict__ WV2,
    const float* __restrict__ f1w,
    const float* __restrict__ f1b,
    const float* __restrict__ f2w,
    const float* __restrict__ f2b,
    float* __restrict__ out)
{
    extern __shared__ float sm[];
    float* sW2 = sm;            // 3 * 6664
    float* sF1 = sm + 19992;    // 6272
    float* sF2 = sm + 26264;    // 160
    float* sB1 = sm + 26424;    // 16
    float* sB2 = sm + 26440;    // 16
    float* sT3 = sm + 26456;    // 8 * 784

    const int tid = threadIdx.x;
    {
        const float* Wg[3] = {WQ2, WK2, WV2};
        for (int w = 0; w < 3; ++w) {
            const float* G = Wg[w];
            float* dst = sW2 + w * 6664;
            for (int idx = tid; idx < 6272; idx += 256) {
                int s = idx >> 7, r = idx & 127, i = r >> 3, d = r & 7;
                dst[s * 136 + i * 8 + d] = G[(s * 8 + d) * 16 + i];
            }
        }
        for (int idx = tid; idx < 6272; idx += 256) {
            int k = idx >> 4, j = idx & 15;
            sF1[idx] = f1w[j * 392 + k];
        }
        for (int idx = tid; idx < 160; idx += 256) {
            int j = idx / 10, c = idx - j * 10;
            sF2[idx] = f2w[c * 16 + j];
        }
        if (tid < 16) sB1[tid] = f1b[tid];
        if (tid < 10) sB2[tid] = f2b[tid];
    }
    __syncthreads();

    const int warpId = tid >> 5;
    const int lane = tid & 31;
    const int hh = lane >> 4;
    const int l16 = lane & 15;
    const int sub = l16 >> 3;   // which patch of the pair
    const int d8 = l16 & 7;     // output dim
    float* t3 = sT3 + warpId * 784 + hh * 392;
    const int totalW = gridDim.x * 8;

    for (int pair = blockIdx.x * 8 + warpId; pair < 8192; pair += totalW) {
        const int b = pair * 2 + hh;
        const float* tb = g_tok2 + (size_t)b * 784;

        float S2[8];
#pragma unroll
        for (int e = 0; e < 8; ++e) S2[e] = 0.f;

        // ---- pass 1: q2,k2 per patch (2 patches per half-warp) ----
#pragma unroll 1
        for (int t = 0; t < 25; ++t) {
            int s = t * 2 + sub;
            int sc = (s < 49) ? s : 48;
            float tt[16];
            const float4* tv = (const float4*)(tb + sc * 16);
#pragma unroll
            for (int t4 = 0; t4 < 4; ++t4) {
                float4 f = tv[t4];
                tt[t4 * 4 + 0] = f.x; tt[t4 * 4 + 1] = f.y;
                tt[t4 * 4 + 2] = f.z; tt[t4 * 4 + 3] = f.w;
            }
            const float* wq = sW2 + sc * 136 + d8;
            const float* wk = wq + 6664;
            float q0 = 0.f, q1 = 0.f, k0 = 0.f, k1 = 0.f;
#pragma unroll
            for (int i = 0; i < 16; i += 2) {
                q0 = fmaf(tt[i], wq[i * 8], q0);
                q1 = fmaf(tt[i + 1], wq[(i + 1) * 8], q1);
                k0 = fmaf(tt[i], wk[i * 8], k0);
                k1 = fmaf(tt[i + 1], wk[(i + 1) * 8], k1);
            }
            float q = q0 + q1;
            float k = k0 + k1;
            if (s >= 49) { q = 0.f; k = 0.f; }
#pragma unroll
            for (int e = 0; e < 8; ++e) {
                float ke = __shfl_sync(FULLMASK, k, e, 8);
                S2[e] = fmaf(q, ke, S2[e]);
            }
        }
        // combine the two sub-group partials, scale by 1/7
#pragma unroll
        for (int e = 0; e < 8; ++e)
            S2[e] = (S2[e] + __shfl_xor_sync(FULLMASK, S2[e], 8, 16)) * (1.f / 7.f);

        // ---- pass 2: v2, apply S2, softmax over 8, tok3 to SMEM ----
#pragma unroll 1
        for (int t = 0; t < 25; ++t) {
            int s = t * 2 + sub;
            int sc = (s < 49) ? s : 48;
            float tt[16];
            const float4* tv = (const float4*)(tb + sc * 16);
#pragma unroll
            for (int t4 = 0; t4 < 4; ++t4) {
                float4 f = tv[t4];
                tt[t4 * 4 + 0] = f.x; tt[t4 * 4 + 1] = f.y;
                tt[t4 * 4 + 2] = f.z; tt[t4 * 4 + 3] = f.w;
            }
            const float* wv = sW2 + 13328 + sc * 136 + d8;
            float v0 = 0.f, v1 = 0.f;
#pragma unroll
            for (int i = 0; i < 16; i += 2) {
                v0 = fmaf(tt[i], wv[i * 8], v0);
                v1 = fmaf(tt[i + 1], wv[(i + 1) * 8], v1);
            }
            float v = v0 + v1;
            float o = 0.f;
#pragma unroll
            for (int e = 0; e < 8; ++e) {
                float ve = __shfl_sync(FULLMASK, v, e, 8);
                o = fmaf(S2[e], ve, o);
            }
            float m = o;
#pragma unroll
            for (int dd = 4; dd; dd >>= 1)
                m = fmaxf(m, __shfl_xor_sync(FULLMASK, m, dd, 8));
            float ex = __expf(o - m);
            float sum = ex;
#pragma unroll
            for (int dd = 4; dd; dd >>= 1)
                sum += __shfl_xor_sync(FULLMASK, sum, dd, 8);
            if (s < 49) t3[s * 8 + d8] = __fdividef(ex, sum);
        }
        __syncwarp();

        // ---- fc1: lane l16 = hidden unit j ----
        float hj = sB1[l16];
        float hj1 = 0.f;
#pragma unroll 8
        for (int k = 0; k < 392; k += 2) {
            hj = fmaf(t3[k], sF1[k * 16 + l16], hj);
            hj1 = fmaf(t3[k + 1], sF1[(k + 1) * 16 + l16], hj1);
        }
        hj = fmaxf(hj + hj1, 0.f);

        // ---- fc2 + softmax over 10 classes ----
        int c = (l16 < 10) ? l16 : 0;
        float lg = sB2[c];
#pragma unroll
        for (int j = 0; j < 16; ++j) {
            float hv = __shfl_sync(FULLMASK, hj, j, 16);
            lg = fmaf(hv, sF2[j * 10 + c], lg);
        }
        if (l16 >= 10) lg = -1e30f;
        float m = lg;
#pragma unroll
        for (int dd = 8; dd; dd >>= 1)
            m = fmaxf(m, __shfl_xor_sync(FULLMASK, m, dd, 16));
        float ex = __expf(lg - m);
        float sum = ex;
#pragma unroll
        for (int dd = 8; dd; dd >>= 1)
            sum += __shfl_xor_sync(FULLMASK, sum, dd, 16);
        if (l16 < 10) out[b * 10 + l16] = __fdividef(ex, sum);
        __syncwarp();  // protect t3 before next iteration rewrites it
    }
}

extern "C" void kernel_launch(void* const* d_in, const int* in_sizes, int n_in,
                              void* d_out, int out_size)
{
    (void)in_sizes; (void)n_in; (void)out_size;
    const float* x   = (const float*)d_in[0];
    const float* pe  = (const float*)d_in[1];
    const float* WQ1 = (const float*)d_in[2];
    const float* WK1 = (const float*)d_in[3];
    const float* WV1 = (const float*)d_in[4];
    const float* WQ2 = (const float*)d_in[5];
    const float* WK2 = (const float*)d_in[6];
    const float* WV2 = (const float*)d_in[7];
    const float* f1w = (const float*)d_in[8];
    const float* f1b = (const float*)d_in[9];
    const float* f2w = (const float*)d_in[10];
    const float* f2b = (const float*)d_in[11];
    float* out = (float*)d_out;

    const size_t smA = (size_t)52528 * sizeof(float);  // 210112 B
    const size_t smB = (size_t)32728 * sizeof(float);  // 130912 B
    cudaFuncSetAttribute(vitA, cudaFuncAttributeMaxDynamicSharedMemorySize, (int)smA);
    cudaFuncSetAttribute(vitB, cudaFuncAttributeMaxDynamicSharedMemorySize, (int)smB);

    vitA<<<148, 256, smA>>>(x, pe, WQ1, WK1, WV1);
    vitB<<<148, 256, smB>>>(WQ2, WK2, WV2, f1w, f1b, f2w, f2b, out);
}

// round 3
// speedup vs baseline: 1.1797x; 1.1797x over previous
#include <cuda_runtime.h>
#include <cstddef>

#define FULLMASK 0xffffffffu

// Global scratch (static __device__ arrays - no allocation at runtime)
static __device__ float g_patch[16384 * 784];      // 51.4 MB patch-major grayscale
static __device__ float g_S[16384 * 256];          // 16.8 MB per-element 16x16 gram
static __device__ float g_tok2[16384 * 49 * 16];   // 51.4 MB stage-1 output

// ---------------------------------------------------------------------------
// Kernel P: grayscale + patch scatter. x (B,3,28,28) -> g_patch [b][s][j]
// Reads fully coalesced; writes 16B-chunked (L2 absorbs).
// ---------------------------------------------------------------------------
__global__ void vitP(const float* __restrict__ x)
{
    int idx = blockIdx.x * 256 + threadIdx.x;
    if (idx >= 16384 * 784) return;
    int b = idx >> 9 ? idx / 784 : idx / 784;  // plain div
    b = idx / 784;
    int p = idx - b * 784;
    const float* xb = x + (size_t)b * 2352;
    float g = 0.299f * xb[p] + 0.587f * xb[784 + p] + 0.114f * xb[1568 + p];
    int py = p / 28, px = p - py * 28;
    g_patch[(size_t)b * 784 + ((py >> 2) * 7 + (px >> 2)) * 16 + ((py & 3) << 2) + (px & 3)] = g;
}

// ---------------------------------------------------------------------------
// Kernel A1: patches -> Q1,K1 (pos-emb folded to bias) -> S gram -> g_S
// SMEM: sW [2][49][16][16] = 25088 floats, sB [2][49][16] = 1568 floats
// total 26656 floats = 106624 B ; 768 threads = 24 warps/SM
// ---------------------------------------------------------------------------
__global__ void __launch_bounds__(768, 1) vitA1(
    const float* __restrict__ pe,
    const float* __restrict__ WQ1,
    const float* __restrict__ WK1)
{
    extern __shared__ float sm[];
    float* sW = sm;          // 2 * 12544
    float* sB = sm + 25088;  // 2 * 784

    const int tid = threadIdx.x;
    {
        const float* Wg[2] = {WQ1, WK1};
        for (int w = 0; w < 2; ++w) {
            const float* G = Wg[w];
            float* dst = sW + w * 12544;
            for (int idx = tid; idx < 12544; idx += 768) {
                int s = idx >> 8, r = idx & 255, i = r >> 4, o = r & 15;
                dst[s * 256 + i * 16 + o] = G[(s * 16 + o) * 32 + i];
            }
            float* db = sB + w * 784;
            for (int idx = tid; idx < 784; idx += 768) {
                int s = idx >> 4, o = idx & 15;
                const float* gw = G + (s * 16 + o) * 32 + 16;
                const float* pp = pe + s * 16;
                float acc = 0.f;
#pragma unroll
                for (int j = 0; j < 16; ++j) acc = fmaf(pp[j], gw[j], acc);
                db[idx] = acc;
            }
        }
    }
    __syncthreads();

    const int warpId = tid >> 5;
    const int lane = tid & 31;
    const int hh = lane >> 4;
    const int l16 = lane & 15;
    const int totalW = gridDim.x * 24;

    for (int pair = blockIdx.x * 24 + warpId; pair < 8192; pair += totalW) {
        const int b = pair * 2 + hh;
        const float* pb = g_patch + (size_t)b * 784;

        float S[16];
#pragma unroll
        for (int e = 0; e < 16; ++e) S[e] = 0.f;

#pragma unroll 1
        for (int s = 0; s < 49; ++s) {
            float pp[16];
            const float4* pv = (const float4*)(pb + s * 16);
#pragma unroll
            for (int t4 = 0; t4 < 4; ++t4) {
                float4 f = __ldg(pv + t4);
                pp[t4 * 4 + 0] = f.x; pp[t4 * 4 + 1] = f.y;
                pp[t4 * 4 + 2] = f.z; pp[t4 * 4 + 3] = f.w;
            }
            const float* wq = sW + s * 256 + l16;
            const float* wk = wq + 12544;
            float q0 = sB[s * 16 + l16], q1 = 0.f;
            float k0 = sB[784 + s * 16 + l16], k1 = 0.f;
#pragma unroll
            for (int i = 0; i < 16; i += 2) {
                q0 = fmaf(pp[i], wq[i * 16], q0);
                q1 = fmaf(pp[i + 1], wq[(i + 1) * 16], q1);
                k0 = fmaf(pp[i], wk[i * 16], k0);
                k1 = fmaf(pp[i + 1], wk[(i + 1) * 16], k1);
            }
            float q = q0 + q1;
            float k = k0 + k1;
#pragma unroll
            for (int e = 0; e < 16; ++e) {
                float ke = __shfl_sync(FULLMASK, k, e, 16);
                S[e] = fmaf(q, ke, S[e]);
            }
        }
        float* sb = g_S + (size_t)b * 256;
#pragma unroll
        for (int e = 0; e < 16; ++e) sb[e * 16 + l16] = S[e] * (1.f / 7.f);
    }
}

// ---------------------------------------------------------------------------
// Kernel A2: patches + S -> V1 -> S@V^T -> softmax -> tok2
// SMEM: sWv [49][256] = 12544, sBv [784] -> 13328 floats = 53312 B
// 768 threads = 24 warps/SM
// ---------------------------------------------------------------------------
__global__ void __launch_bounds__(768, 1) vitA2(
    const float* __restrict__ pe,
    const float* __restrict__ WV1)
{
    extern __shared__ float sm[];
    float* sWv = sm;          // 12544
    float* sBv = sm + 12544;  // 784

    const int tid = threadIdx.x;
    for (int idx = tid; idx < 12544; idx += 768) {
        int s = idx >> 8, r = idx & 255, i = r >> 4, o = r & 15;
        sWv[s * 256 + i * 16 + o] = WV1[(s * 16 + o) * 32 + i];
    }
    for (int idx = tid; idx < 784; idx += 768) {
        int s = idx >> 4, o = idx & 15;
        const float* gw = WV1 + (s * 16 + o) * 32 + 16;
        const float* pp = pe + s * 16;
        float acc = 0.f;
#pragma unroll
        for (int j = 0; j < 16; ++j) acc = fmaf(pp[j], gw[j], acc);
        sBv[idx] = acc;
    }
    __syncthreads();

    const int warpId = tid >> 5;
    const int lane = tid & 31;
    const int hh = lane >> 4;
    const int l16 = lane & 15;
    const int totalW = gridDim.x * 24;

    for (int pair = blockIdx.x * 24 + warpId; pair < 8192; pair += totalW) {
        const int b = pair * 2 + hh;
        const float* pb = g_patch + (size_t)b * 784;
        const float* sgb = g_S + (size_t)b * 256;

        float S[16];
#pragma unroll
        for (int e = 0; e < 16; ++e) S[e] = __ldg(sgb + e * 16 + l16);

        float* ob = g_tok2 + (size_t)b * 784;
#pragma unroll 1
        for (int s = 0; s < 49; ++s) {
            float pp[16];
            const float4* pv = (const float4*)(pb + s * 16);
#pragma unroll
            for (int t4 = 0; t4 < 4; ++t4) {
                float4 f = __ldg(pv + t4);
                pp[t4 * 4 + 0] = f.x; pp[t4 * 4 + 1] = f.y;
                pp[t4 * 4 + 2] = f.z; pp[t4 * 4 + 3] = f.w;
            }
            const float* wv = sWv + s * 256 + l16;
            float v0 = sBv[s * 16 + l16], v1 = 0.f;
#pragma unroll
            for (int i = 0; i < 16; i += 2) {
                v0 = fmaf(pp[i], wv[i * 16], v0);
                v1 = fmaf(pp[i + 1], wv[(i + 1) * 16], v1);
            }
            float v = v0 + v1;
            float o = 0.f;
#pragma unroll
            for (int e = 0; e < 16; ++e) {
                float ve = __shfl_sync(FULLMASK, v, e, 16);
                o = fmaf(S[e], ve, o);
            }
            float m = o;
#pragma unroll
            for (int dd = 8; dd; dd >>= 1)
                m = fmaxf(m, __shfl_xor_sync(FULLMASK, m, dd, 16));
            float ex = __expf(o - m);
            float sum = ex;
#pragma unroll
            for (int dd = 8; dd; dd >>= 1)
                sum += __shfl_xor_sync(FULLMASK, sum, dd, 16);
            ob[s * 16 + l16] = __fdividef(ex, sum);
        }
    }
}

// ---------------------------------------------------------------------------
// Kernel B: tok2 -> QKV2 -> attn(8) -> softmax -> tok3 -> fc1 -> relu -> fc2
// -> softmax -> out.  768 threads = 24 warps/SM.
// SMEM: sW2 3*6664=19992, sF1 6272, sF2 160, sB1 16, sB2 16, sT3 24*784=18816
// total 45272 floats = 181088 B
// ---------------------------------------------------------------------------
__global__ void __launch_bounds__(768, 1) vitB(
    const float* __restrict__ WQ2,
    const float* __restrict__ WK2,
    const float* __restrict__ WV2,
    const float* __restrict__ f1w,
    const float* __restrict__ f1b,
    const float* __restrict__ f2w,
    const float* __restrict__ f2b,
    float* __restrict__ out)
{
    extern __shared__ float sm[];
    float* sW2 = sm;            // 3 * 6664
    float* sF1 = sm + 19992;    // 6272
    float* sF2 = sm + 26264;    // 160
    float* sB1 = sm + 26424;    // 16
    float* sB2 = sm + 26440;    // 16
    float* sT3 = sm + 26456;    // 24 * 784

    const int tid = threadIdx.x;
    {
        const float* Wg[3] = {WQ2, WK2, WV2};
        for (int w = 0; w < 3; ++w) {
            const float* G = Wg[w];
            float* dst = sW2 + w * 6664;
            for (int idx = tid; idx < 6272; idx += 768) {
                int s = idx >> 7, r = idx & 127, i = r >> 3, d = r & 7;
                dst[s * 136 + i * 8 + d] = G[(s * 8 + d) * 16 + i];
            }
        }
        for (int idx = tid; idx < 6272; idx += 768) {
            int k = idx >> 4, j = idx & 15;
            sF1[idx] = f1w[j * 392 + k];
        }
        for (int idx = tid; idx < 160; idx += 768) {
            int j = idx / 10, c = idx - j * 10;
            sF2[idx] = f2w[c * 16 + j];
        }
        if (tid < 16) sB1[tid] = f1b[tid];
        if (tid < 10) sB2[tid] = f2b[tid];
    }
    __syncthreads();

    const int warpId = tid >> 5;
    const int lane = tid & 31;
    const int hh = lane >> 4;
    const int l16 = lane & 15;
    const int sub = l16 >> 3;
    const int d8 = l16 & 7;
    float* t3 = sT3 + warpId * 784 + hh * 392;
    const int totalW = gridDim.x * 24;

    for (int pair = blockIdx.x * 24 + warpId; pair < 8192; pair += totalW) {
        const int b = pair * 2 + hh;
        const float* tb = g_tok2 + (size_t)b * 784;

        float S2[8];
#pragma unroll
        for (int e = 0; e < 8; ++e) S2[e] = 0.f;

#pragma unroll 1
        for (int t = 0; t < 25; ++t) {
            int s = t * 2 + sub;
            int sc = (s < 49) ? s : 48;
            float tt[16];
            const float4* tv = (const float4*)(tb + sc * 16);
#pragma unroll
            for (int t4 = 0; t4 < 4; ++t4) {
                float4 f = __ldg(tv + t4);
                tt[t4 * 4 + 0] = f.x; tt[t4 * 4 + 1] = f.y;
                tt[t4 * 4 + 2] = f.z; tt[t4 * 4 + 3] = f.w;
            }
            const float* wq = sW2 + sc * 136 + d8;
            const float* wk = wq + 6664;
            float q0 = 0.f, q1 = 0.f, k0 = 0.f, k1 = 0.f;
#pragma unroll
            for (int i = 0; i < 16; i += 2) {
                q0 = fmaf(tt[i], wq[i * 8], q0);
                q1 = fmaf(tt[i + 1], wq[(i + 1) * 8], q1);
                k0 = fmaf(tt[i], wk[i * 8], k0);
                k1 = fmaf(tt[i + 1], wk[(i + 1) * 8], k1);
            }
            float q = q0 + q1;
            float k = k0 + k1;
            if (s >= 49) { q = 0.f; k = 0.f; }
#pragma unroll
            for (int e = 0; e < 8; ++e) {
                float ke = __shfl_sync(FULLMASK, k, e, 8);
                S2[e] = fmaf(q, ke, S2[e]);
            }
        }
#pragma unroll
        for (int e = 0; e < 8; ++e)
            S2[e] = (S2[e] + __shfl_xor_sync(FULLMASK, S2[e], 8, 16)) * (1.f / 7.f);

#pragma unroll 1
        for (int t = 0; t < 25; ++t) {
            int s = t * 2 + sub;
            int sc = (s < 49) ? s : 48;
            float tt[16];
            const float4* tv = (const float4*)(tb + sc * 16);
#pragma unroll
            for (int t4 = 0; t4 < 4; ++t4) {
                float4 f = __ldg(tv + t4);
                tt[t4 * 4 + 0] = f.x; tt[t4 * 4 + 1] = f.y;
                tt[t4 * 4 + 2] = f.z; tt[t4 * 4 + 3] = f.w;
            }
            const float* wv = sW2 + 13328 + sc * 136 + d8;
            float v0 = 0.f, v1 = 0.f;
#pragma unroll
            for (int i = 0; i < 16; i += 2) {
                v0 = fmaf(tt[i], wv[i * 8], v0);
                v1 = fmaf(tt[i + 1], wv[(i + 1) * 8], v1);
            }
            float v = v0 + v1;
            float o = 0.f;
#pragma unroll
            for (int e = 0; e < 8; ++e) {
                float ve = __shfl_sync(FULLMASK, v, e, 8);
                o = fmaf(S2[e], ve, o);
            }
            float m = o;
#pragma unroll
            for (int dd = 4; dd; dd >>= 1)
                m = fmaxf(m, __shfl_xor_sync(FULLMASK, m, dd, 8));
            float ex = __expf(o - m);
            float sum = ex;
#pragma unroll
            for (int dd = 4; dd; dd >>= 1)
                sum += __shfl_xor_sync(FULLMASK, sum, dd, 8);
            if (s < 49) t3[s * 8 + d8] = __fdividef(ex, sum);
        }
        __syncwarp();

        float hj = sB1[l16];
        float hj1 = 0.f;
#pragma unroll 8
        for (int k = 0; k < 392; k += 2) {
            hj = fmaf(t3[k], sF1[k * 16 + l16], hj);
            hj1 = fmaf(t3[k + 1], sF1[(k + 1) * 16 + l16], hj1);
        }
        hj = fmaxf(hj + hj1, 0.f);

        int c = (l16 < 10) ? l16 : 0;
        float lg = sB2[c];
#pragma unroll
        for (int j = 0; j < 16; ++j) {
            float hv = __shfl_sync(FULLMASK, hj, j, 16);
            lg = fmaf(hv, sF2[j * 10 + c], lg);
        }
        if (l16 >= 10) lg = -1e30f;
        float m = lg;
#pragma unroll
        for (int dd = 8; dd; dd >>= 1)
            m = fmaxf(m, __shfl_xor_sync(FULLMASK, m, dd, 16));
        float ex = __expf(lg - m);
        float sum = ex;
#pragma unroll
        for (int dd = 8; dd; dd >>= 1)
            sum += __shfl_xor_sync(FULLMASK, sum, dd, 16);
        if (l16 < 10) out[b * 10 + l16] = __fdividef(ex, sum);
        __syncwarp();
    }
}

extern "C" void kernel_launch(void* const* d_in, const int* in_sizes, int n_in,
                              void* d_out, int out_size)
{
    (void)in_sizes; (void)n_in; (void)out_size;
    const float* x   = (const float*)d_in[0];
    const float* pe  = (const float*)d_in[1];
    const float* WQ1 = (const float*)d_in[2];
    const float* WK1 = (const float*)d_in[3];
    const float* WV1 = (const float*)d_in[4];
    const float* WQ2 = (const float*)d_in[5];
    const float* WK2 = (const float*)d_in[6];
    const float* WV2 = (const float*)d_in[7];
    const float* f1w = (const float*)d_in[8];
    const float* f1b = (const float*)d_in[9];
    const float* f2w = (const float*)d_in[10];
    const float* f2b = (const float*)d_in[11];
    float* out = (float*)d_out;

    const size_t smA1 = (size_t)26656 * sizeof(float);  // 106624 B
    const size_t smA2 = (size_t)13328 * sizeof(float);  // 53312 B
    const size_t smB  = (size_t)45272 * sizeof(float);  // 181088 B
    cudaFuncSetAttribute(vitA1, cudaFuncAttributeMaxDynamicSharedMemorySize, (int)smA1);
    cudaFuncSetAttribute(vitA2, cudaFuncAttributeMaxDynamicSharedMemorySize, (int)smA2);
    cudaFuncSetAttribute(vitB,  cudaFuncAttributeMaxDynamicSharedMemorySize, (int)smB);

    vitP<<<(16384 * 784 + 255) / 256, 256>>>(x);
    vitA1<<<148, 768, smA1>>>(pe, WQ1, WK1);
    vitA2<<<148, 768, smA2>>>(pe, WV1);
    vitB<<<148, 768, smB>>>(WQ2, WK2, WV2, f1w, f1b, f2w, f2b, out);
}

// round 4
// speedup vs baseline: 1.3790x; 1.1689x over previous
#include <cuda_runtime.h>
#include <cstddef>

#define FULLMASK 0xffffffffu

// Global scratch (static __device__ arrays - no allocation at runtime)
static __device__ float g_patch[16384 * 784];      // 51.4 MB patch-major grayscale
static __device__ float g_S[16384 * 256];          // 16.8 MB per-element 16x16 gram (layout [b][d][e])
static __device__ float g_tok2[16384 * 49 * 16];   // 51.4 MB stage-1 output

// ---------------------------------------------------------------------------
// Kernel P: grayscale + patch scatter. x (B,3,28,28) -> g_patch [b][s][j]
// ---------------------------------------------------------------------------
__global__ void vitP(const float* __restrict__ x)
{
    int idx = blockIdx.x * 256 + threadIdx.x;
    if (idx >= 16384 * 784) return;
    int b = idx / 784;
    int p = idx - b * 784;
    const float* xb = x + (size_t)b * 2352;
    float g = 0.299f * xb[p] + 0.587f * xb[784 + p] + 0.114f * xb[1568 + p];
    int py = p / 28, px = p - py * 28;
    g_patch[(size_t)b * 784 + ((py >> 2) * 7 + (px >> 2)) * 16 + ((py & 3) << 2) + (px & 3)] = g;
}

// Helper macro: accumulate 16 FMAs of a float4-quad weight block against pp
#define FMA16(acc0, acc1, W0, W1, W2, W3)                                   \
    acc0 = fmaf(p0.x, W0.x, acc0); acc1 = fmaf(p0.y, W0.y, acc1);           \
    acc0 = fmaf(p0.z, W0.z, acc0); acc1 = fmaf(p0.w, W0.w, acc1);           \
    acc0 = fmaf(p1.x, W1.x, acc0); acc1 = fmaf(p1.y, W1.y, acc1);           \
    acc0 = fmaf(p1.z, W1.z, acc0); acc1 = fmaf(p1.w, W1.w, acc1);           \
    acc0 = fmaf(p2.x, W2.x, acc0); acc1 = fmaf(p2.y, W2.y, acc1);           \
    acc0 = fmaf(p2.z, W2.z, acc0); acc1 = fmaf(p2.w, W2.w, acc1);           \
    acc0 = fmaf(p3.x, W3.x, acc0); acc1 = fmaf(p3.y, W3.y, acc1);           \
    acc0 = fmaf(p3.z, W3.z, acc0); acc1 = fmaf(p3.w, W3.w, acc1);

// ---------------------------------------------------------------------------
// Kernel A1: patches -> Q1,K1 (pos-emb folded to bias) -> S gram -> g_S
// Weight layout [w][s][i/4][d][4] : lane d loads 4x LDS.128 per matrix per s.
// One element per warp; half-warps split the s range (25/24).
// SMEM: 2*12544 + 2*784 = 26656 floats = 106624 B. 768 threads.
// ---------------------------------------------------------------------------
__global__ void __launch_bounds__(768, 1) vitA1(
    const float* __restrict__ pe,
    const float* __restrict__ WQ1,
    const float* __restrict__ WK1)
{
    extern __shared__ float sm[];
    float* sW = sm;          // 2 * 12544
    float* sB = sm + 25088;  // 2 * 784

    const int tid = threadIdx.x;
    {
        const float* Wg[2] = {WQ1, WK1};
        for (int w = 0; w < 2; ++w) {
            const float* G = Wg[w];
            float* dst = sW + w * 12544;
            for (int idx = tid; idx < 12544; idx += 768) {
                int s = idx >> 8, r = idx & 255, i = r >> 4, o = r & 15;
                dst[s * 256 + (i >> 2) * 64 + o * 4 + (i & 3)] = G[(s * 16 + o) * 32 + i];
            }
            float* db = sB + w * 784;
            for (int idx = tid; idx < 784; idx += 768) {
                int s = idx >> 4, o = idx & 15;
                const float* gw = G + (s * 16 + o) * 32 + 16;
                const float* pp = pe + s * 16;
                float acc = 0.f;
#pragma unroll
                for (int j = 0; j < 16; ++j) acc = fmaf(pp[j], gw[j], acc);
                db[idx] = acc;
            }
        }
    }
    __syncthreads();

    const int warpId = tid >> 5;
    const int lane = tid & 31;
    const int hh = lane >> 4;
    const int l16 = lane & 15;

    for (int elem = blockIdx.x * 24 + warpId; elem < 16384; elem += 3552) {
        const float* pb = g_patch + (size_t)elem * 784;

        float S[16];
#pragma unroll
        for (int e = 0; e < 16; ++e) S[e] = 0.f;

#pragma unroll 1
        for (int t = 0; t < 25; ++t) {
            int s = hh * 25 + t;
            int sc = (s < 49) ? s : 48;
            const float4* pv = (const float4*)(pb + sc * 16);
            float4 p0 = __ldg(pv + 0), p1 = __ldg(pv + 1);
            float4 p2 = __ldg(pv + 2), p3 = __ldg(pv + 3);

            const float4* wq4 = (const float4*)(sW + sc * 256 + l16 * 4);
            float4 a0 = wq4[0], a1 = wq4[16], a2 = wq4[32], a3 = wq4[48];
            float q0 = sB[sc * 16 + l16], q1 = 0.f;
            FMA16(q0, q1, a0, a1, a2, a3);

            const float4* wk4 = (const float4*)(sW + 12544 + sc * 256 + l16 * 4);
            float4 b0 = wk4[0], b1 = wk4[16], b2 = wk4[32], b3 = wk4[48];
            float k0 = sB[784 + sc * 16 + l16], k1 = 0.f;
            FMA16(k0, k1, b0, b1, b2, b3);

            float q = q0 + q1;
            float k = k0 + k1;
            if (s >= 49) { q = 0.f; k = 0.f; }
#pragma unroll
            for (int e = 0; e < 16; ++e) {
                float ke = __shfl_sync(FULLMASK, k, e, 16);
                S[e] = fmaf(q, ke, S[e]);
            }
        }
#pragma unroll
        for (int e = 0; e < 16; ++e)
            S[e] = (S[e] + __shfl_xor_sync(FULLMASK, S[e], 16)) * (1.f / 7.f);

        // store as [d][e], lane d = l16; each half stores 8 e-values (2x STG.128)
        float* sb = g_S + (size_t)elem * 256 + l16 * 16;
        if (hh == 0) {
            *(float4*)(sb + 0) = make_float4(S[0], S[1], S[2], S[3]);
            *(float4*)(sb + 4) = make_float4(S[4], S[5], S[6], S[7]);
        } else {
            *(float4*)(sb + 8)  = make_float4(S[8], S[9], S[10], S[11]);
            *(float4*)(sb + 12) = make_float4(S[12], S[13], S[14], S[15]);
        }
    }
}

// ---------------------------------------------------------------------------
// Kernel A2: patches + S -> V1 -> S@V^T -> softmax -> tok2
// SMEM: 12544 + 784 = 13328 floats = 53312 B. 768 threads.
// ---------------------------------------------------------------------------
__global__ void __launch_bounds__(768, 1) vitA2(
    const float* __restrict__ pe,
    const float* __restrict__ WV1)
{
    extern __shared__ float sm[];
    float* sWv = sm;          // 12544
    float* sBv = sm + 12544;  // 784

    const int tid = threadIdx.x;
    for (int idx = tid; idx < 12544; idx += 768) {
        int s = idx >> 8, r = idx & 255, i = r >> 4, o = r & 15;
        sWv[s * 256 + (i >> 2) * 64 + o * 4 + (i & 3)] = WV1[(s * 16 + o) * 32 + i];
    }
    for (int idx = tid; idx < 784; idx += 768) {
        int s = idx >> 4, o = idx & 15;
        const float* gw = WV1 + (s * 16 + o) * 32 + 16;
        const float* pp = pe + s * 16;
        float acc = 0.f;
#pragma unroll
        for (int j = 0; j < 16; ++j) acc = fmaf(pp[j], gw[j], acc);
        sBv[idx] = acc;
    }
    __syncthreads();

    const int warpId = tid >> 5;
    const int lane = tid & 31;
    const int hh = lane >> 4;
    const int l16 = lane & 15;

    for (int elem = blockIdx.x * 24 + warpId; elem < 16384; elem += 3552) {
        const float* pb = g_patch + (size_t)elem * 784;
        const float* sgb = g_S + (size_t)elem * 256 + l16 * 16;

        float S[16];
        {
            float4 s0 = __ldg((const float4*)sgb + 0);
            float4 s1 = __ldg((const float4*)sgb + 1);
            float4 s2 = __ldg((const float4*)sgb + 2);
            float4 s3 = __ldg((const float4*)sgb + 3);
            S[0] = s0.x; S[1] = s0.y; S[2] = s0.z; S[3] = s0.w;
            S[4] = s1.x; S[5] = s1.y; S[6] = s1.z; S[7] = s1.w;
            S[8] = s2.x; S[9] = s2.y; S[10] = s2.z; S[11] = s2.w;
            S[12] = s3.x; S[13] = s3.y; S[14] = s3.z; S[15] = s3.w;
        }

        float* ob = g_tok2 + (size_t)elem * 784;
#pragma unroll 1
        for (int t = 0; t < 25; ++t) {
            int s = hh * 25 + t;
            int sc = (s < 49) ? s : 48;
            const float4* pv = (const float4*)(pb + sc * 16);
            float4 p0 = __ldg(pv + 0), p1 = __ldg(pv + 1);
            float4 p2 = __ldg(pv + 2), p3 = __ldg(pv + 3);

            const float4* wv4 = (const float4*)(sWv + sc * 256 + l16 * 4);
            float4 a0 = wv4[0], a1 = wv4[16], a2 = wv4[32], a3 = wv4[48];
            float v0 = sBv[sc * 16 + l16], v1 = 0.f;
            FMA16(v0, v1, a0, a1, a2, a3);
            float v = v0 + v1;

            float o = 0.f;
#pragma unroll
            for (int e = 0; e < 16; ++e) {
                float ve = __shfl_sync(FULLMASK, v, e, 16);
                o = fmaf(S[e], ve, o);
            }
            float m = o;
#pragma unroll
            for (int dd = 8; dd; dd >>= 1)
                m = fmaxf(m, __shfl_xor_sync(FULLMASK, m, dd, 16));
            float ex = __expf(o - m);
            float sum = ex;
#pragma unroll
            for (int dd = 8; dd; dd >>= 1)
                sum += __shfl_xor_sync(FULLMASK, sum, dd, 16);
            if (s < 49) ob[s * 16 + l16] = __fdividef(ex, sum);
        }
    }
}

// ---------------------------------------------------------------------------
// Kernel B: tok2 -> QKV2 -> attn(8) -> softmax -> tok3 -> fc1 -> relu -> fc2
// One element per warp; 4 squads of 8 lanes split s; halves split fc1 k-range.
// Weights [w][s][i/4][d8][4]; fc1 [k/4][j][4].
// SMEM: 3*6272 + 6272 + 160 + 32 + 24*392 = 34688 floats = 138752 B. 768 thr.
// ---------------------------------------------------------------------------
__global__ void __launch_bounds__(768, 1) vitB(
    const float* __restrict__ WQ2,
    const float* __restrict__ WK2,
    const float* __restrict__ WV2,
    const float* __restrict__ f1w,
    const float* __restrict__ f1b,
    const float* __restrict__ f2w,
    const float* __restrict__ f2b,
    float* __restrict__ out)
{
    extern __shared__ float sm[];
    float* sW2 = sm;            // 3 * 6272
    float* sF1 = sm + 18816;    // 6272
    float* sF2 = sm + 25088;    // 160
    float* sB1 = sm + 25248;    // 16
    float* sB2 = sm + 25264;    // 16
    float* sT3 = sm + 25280;    // 24 * 392

    const int tid = threadIdx.x;
    {
        const float* Wg[3] = {WQ2, WK2, WV2};
        for (int w = 0; w < 3; ++w) {
            const float* G = Wg[w];
            float* dst = sW2 + w * 6272;
            for (int idx = tid; idx < 6272; idx += 768) {
                int s = idx >> 7, r = idx & 127, i = r >> 3, d = r & 7;
                dst[s * 128 + (i >> 2) * 32 + d * 4 + (i & 3)] = G[(s * 8 + d) * 16 + i];
            }
        }
        for (int idx = tid; idx < 6272; idx += 768) {
            int k = idx >> 4, j = idx & 15;
            sF1[(k >> 2) * 64 + j * 4 + (k & 3)] = f1w[j * 392 + k];
        }
        for (int idx = tid; idx < 160; idx += 768) {
            int j = idx / 10, c = idx - j * 10;
            sF2[idx] = f2w[c * 16 + j];
        }
        if (tid < 16) sB1[tid] = f1b[tid];
        if (tid < 10) sB2[tid] = f2b[tid];
    }
    __syncthreads();

    const int warpId = tid >> 5;
    const int lane = tid & 31;
    const int hh = lane >> 4;
    const int l16 = lane & 15;
    const int squad = lane >> 3;   // 0..3
    const int d8 = lane & 7;
    float* t3 = sT3 + warpId * 392;

    for (int elem = blockIdx.x * 24 + warpId; elem < 16384; elem += 3552) {
        const float* tb = g_tok2 + (size_t)elem * 784;

        float S2[8];
#pragma unroll
        for (int e = 0; e < 8; ++e) S2[e] = 0.f;

        // ---- pass 1: q2,k2 -> S gram (squads split s) ----
#pragma unroll 1
        for (int t = 0; t < 13; ++t) {
            int s = t * 4 + squad;
            int sc = (s < 49) ? s : 48;
            const float4* pv = (const float4*)(tb + sc * 16);
            float4 p0 = __ldg(pv + 0), p1 = __ldg(pv + 1);
            float4 p2 = __ldg(pv + 2), p3 = __ldg(pv + 3);

            const float4* wq4 = (const float4*)(sW2 + sc * 128 + d8 * 4);
            float4 a0 = wq4[0], a1 = wq4[8], a2 = wq4[16], a3 = wq4[24];
            float q0 = 0.f, q1 = 0.f;
            FMA16(q0, q1, a0, a1, a2, a3);

            const float4* wk4 = (const float4*)(sW2 + 6272 + sc * 128 + d8 * 4);
            float4 b0 = wk4[0], b1 = wk4[8], b2 = wk4[16], b3 = wk4[24];
            float k0 = 0.f, k1 = 0.f;
            FMA16(k0, k1, b0, b1, b2, b3);

            float q = q0 + q1;
            float k = k0 + k1;
            if (s >= 49) { q = 0.f; k = 0.f; }
#pragma unroll
            for (int e = 0; e < 8; ++e) {
                float ke = __shfl_sync(FULLMASK, k, e, 8);
                S2[e] = fmaf(q, ke, S2[e]);
            }
        }
#pragma unroll
        for (int e = 0; e < 8; ++e) {
            float v = S2[e] + __shfl_xor_sync(FULLMASK, S2[e], 8);
            v = v + __shfl_xor_sync(FULLMASK, v, 16);
            S2[e] = v * (1.f / 7.f);
        }

        // ---- pass 2: v2 -> apply S2 -> softmax(8) -> t3 ----
#pragma unroll 1
        for (int t = 0; t < 13; ++t) {
            int s = t * 4 + squad;
            int sc = (s < 49) ? s : 48;
            const float4* pv = (const float4*)(tb + sc * 16);
            float4 p0 = __ldg(pv + 0), p1 = __ldg(pv + 1);
            float4 p2 = __ldg(pv + 2), p3 = __ldg(pv + 3);

            const float4* wv4 = (const float4*)(sW2 + 12544 + sc * 128 + d8 * 4);
            float4 a0 = wv4[0], a1 = wv4[8], a2 = wv4[16], a3 = wv4[24];
            float v0 = 0.f, v1 = 0.f;
            FMA16(v0, v1, a0, a1, a2, a3);
            float v = v0 + v1;

            float o = 0.f;
#pragma unroll
            for (int e = 0; e < 8; ++e) {
                float ve = __shfl_sync(FULLMASK, v, e, 8);
                o = fmaf(S2[e], ve, o);
            }
            float m = o;
#pragma unroll
            for (int dd = 4; dd; dd >>= 1)
                m = fmaxf(m, __shfl_xor_sync(FULLMASK, m, dd, 8));
            float ex = __expf(o - m);
            float sum = ex;
#pragma unroll
            for (int dd = 4; dd; dd >>= 1)
                sum += __shfl_xor_sync(FULLMASK, sum, dd, 8);
            if (s < 49) t3[s * 8 + d8] = __fdividef(ex, sum);  // = t3[t*32+lane]
        }
        __syncwarp();

        // ---- fc1: lane j = l16; halves split k4 range (49 each of 98) ----
        float h0 = 0.f, h1 = 0.f;
        {
            const float* t3h = t3 + hh * 196;
            const float4* w4 = (const float4*)(sF1 + hh * 49 * 64 + l16 * 4);
#pragma unroll 7
            for (int k4 = 0; k4 < 49; ++k4) {
                float4 tv = *(const float4*)(t3h + k4 * 4);
                float4 wv = w4[k4 * 16];
                h0 = fmaf(tv.x, wv.x, h0);
                h1 = fmaf(tv.y, wv.y, h1);
                h0 = fmaf(tv.z, wv.z, h0);
                h1 = fmaf(tv.w, wv.w, h1);
            }
        }
        float hj = h0 + h1;
        hj += __shfl_xor_sync(FULLMASK, hj, 16);
        hj = fmaxf(hj + sB1[l16], 0.f);

        // ---- fc2 + softmax over 10 ----
        int c = (l16 < 10) ? l16 : 0;
        float lg = sB2[c];
#pragma unroll
        for (int j = 0; j < 16; ++j) {
            float hv = __shfl_sync(FULLMASK, hj, j, 16);
            lg = fmaf(hv, sF2[j * 10 + c], lg);
        }
        if (l16 >= 10) lg = -1e30f;
        float m = lg;
#pragma unroll
        for (int dd = 8; dd; dd >>= 1)
            m = fmaxf(m, __shfl_xor_sync(FULLMASK, m, dd, 16));
        float ex = __expf(lg - m);
        float sum = ex;
#pragma unroll
        for (int dd = 8; dd; dd >>= 1)
            sum += __shfl_xor_sync(FULLMASK, sum, dd, 16);
        if (hh == 0 && l16 < 10) out[elem * 10 + l16] = __fdividef(ex, sum);
        __syncwarp();
    }
}

extern "C" void kernel_launch(void* const* d_in, const int* in_sizes, int n_in,
                              void* d_out, int out_size)
{
    (void)in_sizes; (void)n_in; (void)out_size;
    const float* x   = (const float*)d_in[0];
    const float* pe  = (const float*)d_in[1];
    const float* WQ1 = (const float*)d_in[2];
    const float* WK1 = (const float*)d_in[3];
    const float* WV1 = (const float*)d_in[4];
    const float* WQ2 = (const float*)d_in[5];
    const float* WK2 = (const float*)d_in[6];
    const float* WV2 = (const float*)d_in[7];
    const float* f1w = (const float*)d_in[8];
    const float* f1b = (const float*)d_in[9];
    const float* f2w = (const float*)d_in[10];
    const float* f2b = (const float*)d_in[11];
    float* out = (float*)d_out;

    const size_t smA1 = (size_t)26656 * sizeof(float);  // 106624 B
    const size_t smA2 = (size_t)13328 * sizeof(float);  // 53312 B
    const size_t smB  = (size_t)34688 * sizeof(float);  // 138752 B
    cudaFuncSetAttribute(vitA1, cudaFuncAttributeMaxDynamicSharedMemorySize, (int)smA1);
    cudaFuncSetAttribute(vitA2, cudaFuncAttributeMaxDynamicSharedMemorySize, (int)smA2);
    cudaFuncSetAttribute(vitB,  cudaFuncAttributeMaxDynamicSharedMemorySize, (int)smB);

    vitP<<<(16384 * 784 + 255) / 256, 256>>>(x);
    vitA1<<<148, 768, smA1>>>(pe, WQ1, WK1);
    vitA2<<<148, 768, smA2>>>(pe, WV1);
    vitB<<<148, 768, smB>>>(WQ2, WK2, WV2, f1w, f1b, f2w, f2b, out);
}